// round 2
// baseline (speedup 1.0000x reference)
#include <cuda_runtime.h>
#include <math.h>

// ---------------- problem constants ----------------
#define B_      32
#define C_IN    128
#define H_      64
#define W_      64
#define K_      8
#define C_OUT   128
#define HID     512      // C_IN * 4
#define HW      (H_*W_)  // 4096
#define PER_B_W (C_OUT*C_IN*9)  // 147456

// ---------------- scratch (device globals; no allocations) ----------------
__device__ float g_pooled[B_ * C_IN];
__device__ float g_alphas[B_ * K_];
__device__ float g_aggb[B_ * C_OUT];
__device__ float g_aggw[(size_t)B_ * PER_B_W];   // 18.9 MB

// ---------------- 1) global average pool ----------------
__global__ __launch_bounds__(256) void pool_kernel(const float* __restrict__ x,
                                                   float* __restrict__ pooled) {
    int bc = blockIdx.x;                 // 0 .. B*C_IN-1
    const float* p = x + (size_t)bc * HW;
    float s = 0.f;
    for (int i = threadIdx.x; i < HW; i += 256) s += p[i];
#pragma unroll
    for (int o = 16; o; o >>= 1) s += __shfl_xor_sync(0xffffffffu, s, o);
    __shared__ float red[8];
    if ((threadIdx.x & 31) == 0) red[threadIdx.x >> 5] = s;
    __syncthreads();
    if (threadIdx.x < 8) {
        s = red[threadIdx.x];
#pragma unroll
        for (int o = 4; o; o >>= 1) s += __shfl_xor_sync(0xffu, s, o);
        if (threadIdx.x == 0) pooled[bc] = s * (1.f / (float)HW);
    }
}

// ---------------- 2) attention MLP + softmax + agg bias ----------------
__global__ __launch_bounds__(512) void attn_kernel(const float* __restrict__ pooled,
                                                   const float* __restrict__ prompt,
                                                   const float* __restrict__ w1,
                                                   const float* __restrict__ b1,
                                                   const float* __restrict__ w2,
                                                   const float* __restrict__ b2,
                                                   const float* __restrict__ kbias,
                                                   float* __restrict__ alphas,
                                                   float* __restrict__ aggb) {
    int b = blockIdx.x;
    int t = threadIdx.x;
    __shared__ float sp[C_IN];
    __shared__ float sh[HID];
    __shared__ float ss[HID];
    __shared__ float sc[K_];
    __shared__ float sal[K_];

    if (t < C_IN) sp[t] = pooled[b * C_IN + t];
    __syncthreads();

    {   // h = relu(pooled @ w1^T + b1) ; w1 is (HID, C_IN)
        const float* wr = w1 + (size_t)t * C_IN;
        float acc = b1[t];
#pragma unroll 8
        for (int i = 0; i < C_IN; i++) acc = fmaf(sp[i], wr[i], acc);
        sh[t] = fmaxf(acc, 0.f);
    }
    __syncthreads();
    {   // s = h @ w2^T + b2 ; w2 is (HID, HID)
        const float* wr = w2 + (size_t)t * HID;
        float acc = b2[t];
#pragma unroll 8
        for (int i = 0; i < HID; i++) acc = fmaf(sh[i], wr[i], acc);
        ss[t] = acc;
    }
    __syncthreads();

    int wrp = t >> 5, lane = t & 31;
    if (wrp < K_) {   // scores[k] = dot(s, prompt[k])
        const float* pr = prompt + (size_t)wrp * HID;
        float acc = 0.f;
        for (int i = lane; i < HID; i += 32) acc = fmaf(ss[i], pr[i], acc);
#pragma unroll
        for (int o = 16; o; o >>= 1) acc += __shfl_xor_sync(0xffffffffu, acc, o);
        if (lane == 0) sc[wrp] = acc;
    }
    __syncthreads();

    if (t == 0) {   // softmax over K=8 (TEMPERATURE = 1)
        float m = sc[0];
#pragma unroll
        for (int k = 1; k < K_; k++) m = fmaxf(m, sc[k]);
        float e[K_], sum = 0.f;
#pragma unroll
        for (int k = 0; k < K_; k++) { e[k] = __expf(sc[k] - m); sum += e[k]; }
        float inv = 1.f / sum;
#pragma unroll
        for (int k = 0; k < K_; k++) { sal[k] = e[k] * inv; alphas[b * K_ + k] = sal[k]; }
    }
    __syncthreads();

    if (t < C_OUT) {   // agg_b = alphas @ kernels_bias
        float acc = 0.f;
#pragma unroll
        for (int k = 0; k < K_; k++) acc = fmaf(sal[k], kbias[k * C_OUT + t], acc);
        aggb[b * C_OUT + t] = acc;
    }
}

// ---------------- 3) aggregate conv weights per sample ----------------
__global__ __launch_bounds__(256) void aggw_kernel(const float* __restrict__ kw,
                                                   const float* __restrict__ alphas,
                                                   float* __restrict__ aggw) {
    int b = blockIdx.y;
    int i = blockIdx.x * 256 + threadIdx.x;   // 0 .. PER_B_W-1
    __shared__ float a[K_];
    if (threadIdx.x < K_) a[threadIdx.x] = alphas[b * K_ + threadIdx.x];
    __syncthreads();
    float acc = 0.f;
#pragma unroll
    for (int k = 0; k < K_; k++) acc = fmaf(a[k], kw[(size_t)k * PER_B_W + i], acc);
    aggw[(size_t)b * PER_B_W + i] = acc;
}

// ---------------- 4) per-sample 3x3 conv ----------------
// block: (b, oc_block of 32, 16x16 spatial tile); 256 threads
// thread: 2x2 pixel quad  x  8 output channels -> 32 fp32 accumulators
#define TH 16
#define TW 16
#define CI_CHUNK 16
#define OC_BLK 32
#define IN_PITCH 20          // 18 cols padded
#define IN_TILE (CI_CHUNK * 18 * IN_PITCH)   // 5760 floats
#define W_TILE  (OC_BLK * CI_CHUNK * 9)      // 4608 floats

__global__ __launch_bounds__(256, 2) void conv_kernel(const float* __restrict__ x,
                                                      const float* __restrict__ aggw,
                                                      const float* __restrict__ aggb,
                                                      float* __restrict__ out) {
    __shared__ float in_s[IN_TILE];
    __shared__ float w_s[W_TILE];

    const int b    = blockIdx.z;
    const int ocb  = blockIdx.y;            // 0..3
    const int tile = blockIdx.x;            // 0..15
    const int tx   = tile & 3, ty = tile >> 2;
    const int tid  = threadIdx.x;
    const int oc_sub = tid >> 6;            // 0..3
    const int slot   = tid & 63;            // 0..63
    const int qx = slot & 7, qy = slot >> 3;
    const int py = qy * 2, px = qx * 2;     // pixel base within tile

    const int gy0 = ty * TH - 1;            // input tile origin (with halo)
    const int gx0 = tx * TW - 1;

    float acc[8][4];
#pragma unroll
    for (int j = 0; j < 8; j++)
#pragma unroll
        for (int p = 0; p < 4; p++) acc[j][p] = 0.f;

    const float* xb = x + (size_t)b * C_IN * HW;
    const float* wb = aggw + (size_t)b * PER_B_W + (size_t)(ocb * OC_BLK) * (C_IN * 9);

    for (int ci0 = 0; ci0 < C_IN; ci0 += CI_CHUNK) {
        // ---- stage input tile: CI_CHUNK x 18 x 18 (zero-padded halo) ----
        for (int idx = tid; idx < CI_CHUNK * 18 * 18; idx += 256) {
            int ci  = idx / (18 * 18);
            int rem = idx - ci * (18 * 18);
            int iy  = rem / 18;
            int ix  = rem - iy * 18;
            int gy = gy0 + iy, gx = gx0 + ix;
            float v = 0.f;
            if ((unsigned)gy < H_ && (unsigned)gx < W_)
                v = xb[((size_t)(ci0 + ci) * H_ + gy) * W_ + gx];
            in_s[ci * (18 * IN_PITCH) + iy * IN_PITCH + ix] = v;
        }
        // ---- stage weights: OC_BLK x CI_CHUNK x 9 ----
        for (int idx = tid; idx < W_TILE; idx += 256) {
            int oc  = idx / (CI_CHUNK * 9);
            int rem = idx - oc * (CI_CHUNK * 9);     // ci*9 + tap
            w_s[idx] = wb[(size_t)oc * (C_IN * 9) + (size_t)ci0 * 9 + rem];
        }
        __syncthreads();

#pragma unroll 1
        for (int ci = 0; ci < CI_CHUNK; ci++) {
            float win[4][4];
            const float* ip = &in_s[ci * (18 * IN_PITCH) + py * IN_PITCH + px];
#pragma unroll
            for (int yy = 0; yy < 4; yy++)
#pragma unroll
                for (int xx = 0; xx < 4; xx++)
                    win[yy][xx] = ip[yy * IN_PITCH + xx];

#pragma unroll
            for (int j = 0; j < 8; j++) {
                const float* wp = &w_s[(oc_sub * 8 + j) * (CI_CHUNK * 9) + ci * 9];
#pragma unroll
                for (int dy = 0; dy < 3; dy++)
#pragma unroll
                    for (int dx = 0; dx < 3; dx++) {
                        float w = wp[dy * 3 + dx];
                        acc[j][0] = fmaf(w, win[dy][dx],         acc[j][0]);
                        acc[j][1] = fmaf(w, win[dy][dx + 1],     acc[j][1]);
                        acc[j][2] = fmaf(w, win[dy + 1][dx],     acc[j][2]);
                        acc[j][3] = fmaf(w, win[dy + 1][dx + 1], acc[j][3]);
                    }
            }
        }
        __syncthreads();
    }

    // ---- epilogue: add bias, store ----
    const int y0 = ty * TH + py;
    const int x0 = tx * TW + px;
#pragma unroll
    for (int j = 0; j < 8; j++) {
        int oc = ocb * OC_BLK + oc_sub * 8 + j;
        float bias = aggb[b * C_OUT + oc];
        float* op = out + (((size_t)b * C_OUT + oc) * H_ + y0) * W_ + x0;
        op[0]      = acc[j][0] + bias;
        op[1]      = acc[j][1] + bias;
        op[W_]     = acc[j][2] + bias;
        op[W_ + 1] = acc[j][3] + bias;
    }
}

// ---------------- launch ----------------
extern "C" void kernel_launch(void* const* d_in, const int* in_sizes, int n_in,
                              void* d_out, int out_size) {
    const float* x      = (const float*)d_in[0];
    const float* prompt = (const float*)d_in[1];
    const float* w1     = (const float*)d_in[2];
    const float* b1     = (const float*)d_in[3];
    const float* w2     = (const float*)d_in[4];
    const float* b2     = (const float*)d_in[5];
    const float* kw     = (const float*)d_in[6];
    const float* kbias  = (const float*)d_in[7];
    float* out = (float*)d_out;

    float *pooled, *alphas, *aggb, *aggw;
    cudaGetSymbolAddress((void**)&pooled, g_pooled);
    cudaGetSymbolAddress((void**)&alphas, g_alphas);
    cudaGetSymbolAddress((void**)&aggb,   g_aggb);
    cudaGetSymbolAddress((void**)&aggw,   g_aggw);

    pool_kernel<<<B_ * C_IN, 256>>>(x, pooled);
    attn_kernel<<<B_, 512>>>(pooled, prompt, w1, b1, w2, b2, kbias, alphas, aggb);
    aggw_kernel<<<dim3(PER_B_W / 256, B_), 256>>>(kw, alphas, aggw);
    conv_kernel<<<dim3(16, C_OUT / OC_BLK, B_), 256>>>(x, aggw, aggb, out);
}

// round 4
// speedup vs baseline: 1.7935x; 1.7935x over previous
#include <cuda_runtime.h>
#include <cuda_bf16.h>
#include <stdint.h>

#define B_    32
#define C_IN  128
#define H_    64
#define W_    64
#define K_    8
#define C_OUT 128
#define HID   512
#define HW    4096

__device__ float g_pooled[B_ * C_IN];
__device__ float g_alphas[B_ * K_];
__device__ float g_aggb[B_ * C_OUT];
// xt layout: [b][cb(8)][pixel(4096)][ci16] bf16  (1,048,576 B per b)
__device__ __nv_bfloat16 g_xt_hi[(size_t)B_ * HW * C_IN];
__device__ __nv_bfloat16 g_xt_lo[(size_t)B_ * HW * C_IN];
// aw layout: [b][tap(9)][cb(8)][oc(128)][ci16] bf16 (294,912 B per b)
__device__ __nv_bfloat16 g_aw_hi[(size_t)B_ * 9 * C_OUT * C_IN];
__device__ __nv_bfloat16 g_aw_lo[(size_t)B_ * 9 * C_OUT * C_IN];

__device__ __forceinline__ uint32_t smem_u32(const void* p) {
    uint32_t a;
    asm("{ .reg .u64 t; cvta.to.shared.u64 t, %1; cvt.u32.u64 %0, t; }" : "=r"(a) : "l"(p));
    return a;
}
#define CPA(dst, src, sz) \
    asm volatile("cp.async.cg.shared.global [%0], [%1], 16, %2;" :: "r"(dst), "l"(src), "r"(sz) : "memory")
#define CP_COMMIT() asm volatile("cp.async.commit_group;" ::: "memory")
#define CP_WAIT1()  asm volatile("cp.async.wait_group 1;" ::: "memory")
#define LDSM4(r, a) \
    asm volatile("ldmatrix.sync.aligned.m8n8.x4.shared.b16 {%0,%1,%2,%3}, [%4];" \
        : "=r"((r)[0]), "=r"((r)[1]), "=r"((r)[2]), "=r"((r)[3]) : "r"(a))
#define LDSM2(r, a) \
    asm volatile("ldmatrix.sync.aligned.m8n8.x2.shared.b16 {%0,%1}, [%2];" \
        : "=r"((r)[0]), "=r"((r)[1]) : "r"(a))
#define MMA(c, a, bb) \
    asm volatile("mma.sync.aligned.m16n8k16.row.col.f32.bf16.bf16.f32 " \
        "{%0,%1,%2,%3}, {%4,%5,%6,%7}, {%8,%9}, {%0,%1,%2,%3};" \
        : "+f"((c)[0]), "+f"((c)[1]), "+f"((c)[2]), "+f"((c)[3]) \
        : "r"((a)[0]), "r"((a)[1]), "r"((a)[2]), "r"((a)[3]), "r"((bb)[0]), "r"((bb)[1]))

// ---------- 1) pool ----------
__global__ __launch_bounds__(256) void pool_kernel(const float* __restrict__ x, float* __restrict__ pooled) {
    int bc = blockIdx.x;
    const float* p = x + (size_t)bc * HW;
    float s = 0.f;
    for (int i = threadIdx.x; i < HW; i += 256) s += p[i];
#pragma unroll
    for (int o = 16; o; o >>= 1) s += __shfl_xor_sync(~0u, s, o);
    __shared__ float red[8];
    if ((threadIdx.x & 31) == 0) red[threadIdx.x >> 5] = s;
    __syncthreads();
    if (threadIdx.x < 8) {
        s = red[threadIdx.x];
#pragma unroll
        for (int o = 4; o; o >>= 1) s += __shfl_xor_sync(0xffu, s, o);
        if (threadIdx.x == 0) pooled[bc] = s * (1.f / (float)HW);
    }
}

// ---------- 2) attention ----------
__global__ __launch_bounds__(512) void attn_kernel(const float* __restrict__ pooled, const float* __restrict__ prompt,
        const float* __restrict__ w1, const float* __restrict__ b1, const float* __restrict__ w2,
        const float* __restrict__ b2, const float* __restrict__ kbias,
        float* __restrict__ alphas, float* __restrict__ aggb) {
    int b = blockIdx.x, t = threadIdx.x;
    __shared__ float sp[C_IN], sh[HID], ss[HID], sc[K_], sal[K_];
    if (t < C_IN) sp[t] = pooled[b * C_IN + t];
    __syncthreads();
    { const float* wr = w1 + (size_t)t * C_IN; float a = b1[t];
#pragma unroll 8
      for (int i = 0; i < C_IN; i++) a = fmaf(sp[i], wr[i], a);
      sh[t] = fmaxf(a, 0.f); }
    __syncthreads();
    { const float* wr = w2 + (size_t)t * HID; float a = b2[t];
#pragma unroll 8
      for (int i = 0; i < HID; i++) a = fmaf(sh[i], wr[i], a);
      ss[t] = a; }
    __syncthreads();
    int wr = t >> 5, ln = t & 31;
    if (wr < K_) {
        const float* pr = prompt + (size_t)wr * HID;
        float a = 0.f;
        for (int i = ln; i < HID; i += 32) a = fmaf(ss[i], pr[i], a);
#pragma unroll
        for (int o = 16; o; o >>= 1) a += __shfl_xor_sync(~0u, a, o);
        if (ln == 0) sc[wr] = a;
    }
    __syncthreads();
    if (t == 0) {
        float m = sc[0];
#pragma unroll
        for (int k = 1; k < K_; k++) m = fmaxf(m, sc[k]);
        float e[K_], su = 0.f;
#pragma unroll
        for (int k = 0; k < K_; k++) { e[k] = __expf(sc[k] - m); su += e[k]; }
        float inv = 1.f / su;
#pragma unroll
        for (int k = 0; k < K_; k++) { sal[k] = e[k] * inv; alphas[b * K_ + k] = sal[k]; }
    }
    __syncthreads();
    if (t < C_OUT) {
        float a = 0.f;
#pragma unroll
        for (int k = 0; k < K_; k++) a = fmaf(sal[k], kbias[k * C_OUT + t], a);
        aggb[b * C_OUT + t] = a;
    }
}

// ---------- 3) weight agg -> [b][tap][cb][oc][ci16] hi/lo ----------
__global__ __launch_bounds__(128) void aggw_bf16_kernel(const float* __restrict__ kw, const float* __restrict__ alphas,
        __nv_bfloat16* __restrict__ Ah, __nv_bfloat16* __restrict__ Al) {
    int oc = blockIdx.x, b = blockIdx.y, ci = threadIdx.x;
    __shared__ float skw[K_][C_IN * 9];
    __shared__ float a[K_];
    if (ci < K_) a[ci] = alphas[b * K_ + ci];
    for (int k = 0; k < K_; k++)
        for (int i = ci; i < C_IN * 9; i += 128)
            skw[k][i] = kw[(size_t)(k * C_OUT + oc) * (C_IN * 9) + i];
    __syncthreads();
    float acc[9];
#pragma unroll
    for (int t = 0; t < 9; t++) acc[t] = 0.f;
#pragma unroll
    for (int k = 0; k < K_; k++) {
        float al = a[k];
        const float* p = &skw[k][ci * 9];
#pragma unroll
        for (int t = 0; t < 9; t++) acc[t] = fmaf(al, p[t], acc[t]);
    }
#pragma unroll
    for (int t = 0; t < 9; t++) {
        float v = acc[t];
        __nv_bfloat16 h = __float2bfloat16(v);
        __nv_bfloat16 l = __float2bfloat16(v - __bfloat162float(h));
        size_t o = ((((size_t)(b * 9 + t) * 8 + (ci >> 4)) * C_OUT) + oc) * 16 + (ci & 15);
        Ah[o] = h; Al[o] = l;
    }
}

// ---------- 4) x -> [b][cb][p][ci16] hi/lo ----------
__global__ __launch_bounds__(256) void xt_split_kernel(const float* __restrict__ x,
        __nv_bfloat16* __restrict__ Xh, __nv_bfloat16* __restrict__ Xl) {
    __shared__ float t[32][33];
    int b = blockIdx.z, p0 = blockIdx.x * 32, c0 = blockIdx.y * 32;
    int tx = threadIdx.x, ty = threadIdx.y;
#pragma unroll
    for (int i = 0; i < 4; i++)
        t[ty + 8 * i][tx] = x[((size_t)b * C_IN + c0 + ty + 8 * i) * HW + p0 + tx];
    __syncthreads();
    int c = c0 + tx;
#pragma unroll
    for (int i = 0; i < 4; i++) {
        int p = p0 + ty + 8 * i;
        float v = t[tx][ty + 8 * i];
        __nv_bfloat16 h = __float2bfloat16(v);
        __nv_bfloat16 l = __float2bfloat16(v - __bfloat162float(h));
        size_t o = (((size_t)b * 8 + (c >> 4)) * HW + p) * 16 + (c & 15);
        Xh[o] = h; Xl[o] = l;
    }
}

// ---------- 5) HMMA conv ----------
// smem per buffer: Ah 128x48 | Al 128x48 | Bh 256x48 | Bl 256x48 = 36864 B, x2
#define SM_AH 0
#define SM_AL 6144
#define SM_BH 12288
#define SM_BL 24576
#define BUF_SZ 36864
#define NSTG 72

__global__ __launch_bounds__(512, 1) void conv_mma_kernel(
        const __nv_bfloat16* __restrict__ awh, const __nv_bfloat16* __restrict__ awl,
        const __nv_bfloat16* __restrict__ xh,  const __nv_bfloat16* __restrict__ xl,
        const float* __restrict__ aggb, float* __restrict__ out)
{
    extern __shared__ __align__(128) char sm[];
    const uint32_t sbase = smem_u32(sm);
    const int b  = blockIdx.x >> 4;
    const int y0 = (blockIdx.x & 15) * 4;
    const int tid = threadIdx.x, wid = tid >> 5, lane = tid & 31;
    const int warp_m = wid & 3, warp_n = wid >> 2;

    // --- per-thread cp.async source/dst ---
    const int aid = tid & 255, aoc = aid >> 1, ah = aid & 1;
    const char* aSrc = (const char*)((tid < 256) ? awh : awl) + (size_t)b * 294912 + aoc * 32 + ah * 16;
    const uint32_t aDst = sbase + ((tid < 256) ? SM_AH : SM_AL) + aoc * 48 + ah * 16;
    const int p = tid >> 1, bh_ = tid & 1;
    const int py = p >> 6, px = p & 63;
    const char* bSrcH = (const char*)xh + (size_t)b * 1048576 + bh_ * 16;
    const char* bSrcL = (const char*)xl + (size_t)b * 1048576 + bh_ * 16;
    const uint32_t bDstH = sbase + SM_BH + p * 48 + bh_ * 16;
    const uint32_t bDstL = sbase + SM_BL + p * 48 + bh_ * 16;

    // --- ldmatrix offsets (relative to buffer base) ---
    const uint32_t offA = (uint32_t)((warp_m * 32 + (lane & 15)) * 48 + (lane >> 4) * 16);
    const uint32_t offB = (uint32_t)((warp_n * 64 + (lane & 7)) * 48 + ((lane >> 3) & 1) * 16);

    float C[8][2][4];
#pragma unroll
    for (int i = 0; i < 8; i++)
#pragma unroll
        for (int j = 0; j < 2; j++)
#pragma unroll
            for (int q = 0; q < 4; q++) C[i][j][q] = 0.f;

#define LOAD_STAGE(s, bufsel) do { \
    int tap_ = (s) >> 3, cb_ = (s) & 7; \
    int dy_ = tap_ / 3 - 1, dx_ = tap_ % 3 - 1; \
    int yy_ = y0 + py + dy_, xx_ = px + dx_; \
    bool v_ = ((unsigned)yy_ < 64u) && ((unsigned)xx_ < 64u); \
    size_t boff_ = (size_t)cb_ * 131072 + (v_ ? (size_t)(yy_ * 64 + xx_) * 32 : 0); \
    unsigned bsz_ = v_ ? 16u : 0u; \
    uint32_t bs_ = (bufsel) * BUF_SZ; \
    CPA(aDst + bs_, aSrc + (size_t)(s) * 4096, 16u); \
    CPA(bDstH + bs_, bSrcH + boff_, bsz_); \
    CPA(bDstL + bs_, bSrcL + boff_, bsz_); \
} while (0)

    LOAD_STAGE(0, 0);
    CP_COMMIT();

    for (int s = 0; s < NSTG; s++) {
        if (s + 1 < NSTG) LOAD_STAGE(s + 1, (s + 1) & 1);
        CP_COMMIT();
        CP_WAIT1();
        __syncthreads();

        const uint32_t bb = sbase + (s & 1) * BUF_SZ;
        uint32_t Ahf[2][4], Alf[2][4];
        LDSM4(Ahf[0], bb + SM_AH + offA);
        LDSM4(Ahf[1], bb + SM_AH + offA + 16 * 48);
        LDSM4(Alf[0], bb + SM_AL + offA);
        LDSM4(Alf[1], bb + SM_AL + offA + 16 * 48);
#pragma unroll
        for (int ntp = 0; ntp < 4; ntp++) {
            uint32_t BH[2][2], BL[2][2];
            LDSM2(BH[0], bb + SM_BH + offB + (2 * ntp) * 8 * 48);
            LDSM2(BH[1], bb + SM_BH + offB + (2 * ntp + 1) * 8 * 48);
            LDSM2(BL[0], bb + SM_BL + offB + (2 * ntp) * 8 * 48);
            LDSM2(BL[1], bb + SM_BL + offB + (2 * ntp + 1) * 8 * 48);
            float (*c0)[4] = C[2 * ntp];
            float (*c1)[4] = C[2 * ntp + 1];
            MMA(c0[0], Ahf[0], BH[0]); MMA(c0[1], Ahf[1], BH[0]);
            MMA(c1[0], Ahf[0], BH[1]); MMA(c1[1], Ahf[1], BH[1]);
            MMA(c0[0], Ahf[0], BL[0]); MMA(c0[1], Ahf[1], BL[0]);
            MMA(c1[0], Ahf[0], BL[1]); MMA(c1[1], Ahf[1], BL[1]);
            MMA(c0[0], Alf[0], BH[0]); MMA(c0[1], Alf[1], BH[0]);
            MMA(c1[0], Alf[0], BH[1]); MMA(c1[1], Alf[1], BH[1]);
        }
        __syncthreads();
    }

    // --- epilogue: warp_n = row within 4-row block, lane cols ---
    const int y = y0 + warp_n;
    float* orow = out + (size_t)b * 128 * HW + y * 64;
#pragma unroll
    for (int mt = 0; mt < 2; mt++) {
        int oc0 = warp_m * 32 + mt * 16 + (lane >> 2);
        float bi0 = aggb[b * 128 + oc0];
        float bi1 = aggb[b * 128 + oc0 + 8];
#pragma unroll
        for (int nt = 0; nt < 8; nt++) {
            int xcol = nt * 8 + 2 * (lane & 3);
            float2 v0 = { C[nt][mt][0] + bi0, C[nt][mt][1] + bi0 };
            float2 v1 = { C[nt][mt][2] + bi1, C[nt][mt][3] + bi1 };
            *(float2*)(orow + (size_t)oc0 * HW + xcol) = v0;
            *(float2*)(orow + (size_t)(oc0 + 8) * HW + xcol) = v1;
        }
    }
}

// ---------- host ----------
extern "C" void kernel_launch(void* const* d_in, const int* in_sizes, int n_in,
                              void* d_out, int out_size) {
    const float* x      = (const float*)d_in[0];
    const float* prompt = (const float*)d_in[1];
    const float* w1     = (const float*)d_in[2];
    const float* b1     = (const float*)d_in[3];
    const float* w2     = (const float*)d_in[4];
    const float* b2     = (const float*)d_in[5];
    const float* kw     = (const float*)d_in[6];
    const float* kbias  = (const float*)d_in[7];
    float* out = (float*)d_out;

    float *pooled, *alphas, *aggb;
    __nv_bfloat16 *xh, *xl, *awh, *awl;
    cudaGetSymbolAddress((void**)&pooled, g_pooled);
    cudaGetSymbolAddress((void**)&alphas, g_alphas);
    cudaGetSymbolAddress((void**)&aggb,   g_aggb);
    cudaGetSymbolAddress((void**)&xh,     g_xt_hi);
    cudaGetSymbolAddress((void**)&xl,     g_xt_lo);
    cudaGetSymbolAddress((void**)&awh,    g_aw_hi);
    cudaGetSymbolAddress((void**)&awl,    g_aw_lo);

    cudaFuncSetAttribute(conv_mma_kernel, cudaFuncAttributeMaxDynamicSharedMemorySize, 2 * BUF_SZ);

    pool_kernel<<<B_ * C_IN, 256>>>(x, pooled);
    attn_kernel<<<B_, 512>>>(pooled, prompt, w1, b1, w2, b2, kbias, alphas, aggb);
    aggw_bf16_kernel<<<dim3(C_OUT, B_), 128>>>(kw, alphas, awh, awl);
    xt_split_kernel<<<dim3(HW / 32, C_IN / 32, B_), dim3(32, 8)>>>(x, xh, xl);
    conv_mma_kernel<<<512, 512, 2 * BUF_SZ>>>(awh, awl, xh, xl, aggb, out);
}

// round 5
// speedup vs baseline: 2.4291x; 1.3544x over previous
#include <cuda_runtime.h>
#include <cuda_fp16.h>
#include <stdint.h>

#define B_    32
#define C_IN  128
#define H_    64
#define W_    64
#define K_    8
#define C_OUT 128
#define HID   512
#define HW    4096

__device__ float g_pooled[B_ * C_IN];
__device__ float g_alphas[B_ * K_];
__device__ float g_aggb[B_ * C_OUT];
// x: [b][cb(8)][pixel(4096)][ci16] fp16   (1,048,576 B per b)
__device__ __half g_xt[(size_t)B_ * HW * C_IN];
// w: [b][tap(9)][cb(8)][oc(128)][ci16] fp16 (294,912 B per b)
__device__ __half g_aw_hi[(size_t)B_ * 9 * C_OUT * C_IN];
__device__ __half g_aw_lo[(size_t)B_ * 9 * C_OUT * C_IN];

__device__ __forceinline__ uint32_t smem_u32(const void* p) {
    uint32_t a;
    asm("{ .reg .u64 t; cvta.to.shared.u64 t, %1; cvt.u32.u64 %0, t; }" : "=r"(a) : "l"(p));
    return a;
}
#define CPA(dst, src, sz) \
    asm volatile("cp.async.cg.shared.global [%0], [%1], 16, %2;" :: "r"(dst), "l"(src), "r"(sz) : "memory")
#define CP_COMMIT() asm volatile("cp.async.commit_group;" ::: "memory")
#define CP_WAIT2()  asm volatile("cp.async.wait_group 2;" ::: "memory")
#define LDSM4(r, a) \
    asm volatile("ldmatrix.sync.aligned.m8n8.x4.shared.b16 {%0,%1,%2,%3}, [%4];" \
        : "=r"((r)[0]), "=r"((r)[1]), "=r"((r)[2]), "=r"((r)[3]) : "r"(a))
#define LDSM2(r, a) \
    asm volatile("ldmatrix.sync.aligned.m8n8.x2.shared.b16 {%0,%1}, [%2];" \
        : "=r"((r)[0]), "=r"((r)[1]) : "r"(a))
#define MMA(c, a, bb) \
    asm volatile("mma.sync.aligned.m16n8k16.row.col.f32.f16.f16.f32 " \
        "{%0,%1,%2,%3}, {%4,%5,%6,%7}, {%8,%9}, {%0,%1,%2,%3};" \
        : "+f"((c)[0]), "+f"((c)[1]), "+f"((c)[2]), "+f"((c)[3]) \
        : "r"((a)[0]), "r"((a)[1]), "r"((a)[2]), "r"((a)[3]), "r"((bb)[0]), "r"((bb)[1]))

// ---------- 1) pool ----------
__global__ __launch_bounds__(256) void pool_kernel(const float* __restrict__ x, float* __restrict__ pooled) {
    int bc = blockIdx.x;
    const float* p = x + (size_t)bc * HW;
    float s = 0.f;
    for (int i = threadIdx.x; i < HW; i += 256) s += p[i];
#pragma unroll
    for (int o = 16; o; o >>= 1) s += __shfl_xor_sync(~0u, s, o);
    __shared__ float red[8];
    if ((threadIdx.x & 31) == 0) red[threadIdx.x >> 5] = s;
    __syncthreads();
    if (threadIdx.x < 8) {
        s = red[threadIdx.x];
#pragma unroll
        for (int o = 4; o; o >>= 1) s += __shfl_xor_sync(0xffu, s, o);
        if (threadIdx.x == 0) pooled[bc] = s * (1.f / (float)HW);
    }
}

// ---------- 2) attention ----------
__global__ __launch_bounds__(512) void attn_kernel(const float* __restrict__ pooled, const float* __restrict__ prompt,
        const float* __restrict__ w1, const float* __restrict__ b1, const float* __restrict__ w2,
        const float* __restrict__ b2, const float* __restrict__ kbias,
        float* __restrict__ alphas, float* __restrict__ aggb) {
    int b = blockIdx.x, t = threadIdx.x;
    __shared__ float sp[C_IN], sh[HID], ss[HID], sc[K_], sal[K_];
    if (t < C_IN) sp[t] = pooled[b * C_IN + t];
    __syncthreads();
    { const float* wr = w1 + (size_t)t * C_IN; float a = b1[t];
#pragma unroll 8
      for (int i = 0; i < C_IN; i++) a = fmaf(sp[i], wr[i], a);
      sh[t] = fmaxf(a, 0.f); }
    __syncthreads();
    { const float* wr = w2 + (size_t)t * HID; float a = b2[t];
#pragma unroll 8
      for (int i = 0; i < HID; i++) a = fmaf(sh[i], wr[i], a);
      ss[t] = a; }
    __syncthreads();
    int wr = t >> 5, ln = t & 31;
    if (wr < K_) {
        const float* pr = prompt + (size_t)wr * HID;
        float a = 0.f;
        for (int i = ln; i < HID; i += 32) a = fmaf(ss[i], pr[i], a);
#pragma unroll
        for (int o = 16; o; o >>= 1) a += __shfl_xor_sync(~0u, a, o);
        if (ln == 0) sc[wr] = a;
    }
    __syncthreads();
    if (t == 0) {
        float m = sc[0];
#pragma unroll
        for (int k = 1; k < K_; k++) m = fmaxf(m, sc[k]);
        float e[K_], su = 0.f;
#pragma unroll
        for (int k = 0; k < K_; k++) { e[k] = __expf(sc[k] - m); su += e[k]; }
        float inv = 1.f / su;
#pragma unroll
        for (int k = 0; k < K_; k++) { sal[k] = e[k] * inv; alphas[b * K_ + k] = sal[k]; }
    }
    __syncthreads();
    if (t < C_OUT) {
        float a = 0.f;
#pragma unroll
        for (int k = 0; k < K_; k++) a = fmaf(sal[k], kbias[k * C_OUT + t], a);
        aggb[b * C_OUT + t] = a;
    }
}

// ---------- 3) weight agg -> [b][tap][cb][oc][ci16] fp16 hi/lo ----------
__global__ __launch_bounds__(128) void aggw_f16_kernel(const float* __restrict__ kw, const float* __restrict__ alphas,
        __half* __restrict__ Ah, __half* __restrict__ Al) {
    int oc = blockIdx.x, b = blockIdx.y, ci = threadIdx.x;
    __shared__ float skw[K_][C_IN * 9];
    __shared__ float a[K_];
    if (ci < K_) a[ci] = alphas[b * K_ + ci];
    for (int k = 0; k < K_; k++)
        for (int i = ci; i < C_IN * 9; i += 128)
            skw[k][i] = kw[(size_t)(k * C_OUT + oc) * (C_IN * 9) + i];
    __syncthreads();
    float acc[9];
#pragma unroll
    for (int t = 0; t < 9; t++) acc[t] = 0.f;
#pragma unroll
    for (int k = 0; k < K_; k++) {
        float al = a[k];
        const float* p = &skw[k][ci * 9];
#pragma unroll
        for (int t = 0; t < 9; t++) acc[t] = fmaf(al, p[t], acc[t]);
    }
#pragma unroll
    for (int t = 0; t < 9; t++) {
        float v = acc[t];
        __half h = __float2half_rn(v);
        __half l = __float2half_rn(v - __half2float(h));
        size_t o = ((((size_t)(b * 9 + t) * 8 + (ci >> 4)) * C_OUT) + oc) * 16 + (ci & 15);
        Ah[o] = h; Al[o] = l;
    }
}

// ---------- 4) x -> [b][cb][p][ci16] fp16 ----------
__global__ __launch_bounds__(256) void xt_f16_kernel(const float* __restrict__ x, __half* __restrict__ X) {
    __shared__ float t[32][33];
    int b = blockIdx.z, p0 = blockIdx.x * 32, c0 = blockIdx.y * 32;
    int tx = threadIdx.x, ty = threadIdx.y;
#pragma unroll
    for (int i = 0; i < 4; i++)
        t[ty + 8 * i][tx] = x[((size_t)b * C_IN + c0 + ty + 8 * i) * HW + p0 + tx];
    __syncthreads();
    int c = c0 + tx;
#pragma unroll
    for (int i = 0; i < 4; i++) {
        int p = p0 + ty + 8 * i;
        size_t o = (((size_t)b * 8 + (c >> 4)) * HW + p) * 16 + (c & 15);
        X[o] = __float2half_rn(t[tx][ty + 8 * i]);
    }
}

// ---------- 5) HMMA conv: fp16 2-pass, 4-stage pipeline ----------
#define PITCH 48
#define SM_AH 0
#define SM_AL 6144
#define SM_B  12288
#define BUF_SZ 24576
#define NSTG 72

__global__ __launch_bounds__(512, 1) void conv_mma_kernel(
        const __half* __restrict__ awh, const __half* __restrict__ awl,
        const __half* __restrict__ xh,
        const float* __restrict__ aggb, float* __restrict__ out)
{
    extern __shared__ __align__(128) char sm[];
    const uint32_t sbase = smem_u32(sm);
    const int b  = blockIdx.x >> 4;
    const int y0 = (blockIdx.x & 15) * 4;
    const int tid = threadIdx.x, wid = tid >> 5, lane = tid & 31;
    const int warp_m = wid & 3, warp_n = wid >> 2;

    // A chunk: 128 rows x {Ah h0, Ah h1, Al h0, Al h1}
    const int ar = tid >> 2, asel = tid & 3;
    const char* aSrc = (const char*)((asel < 2) ? awh : awl) + (size_t)b * 294912 + ar * 32 + (asel & 1) * 16;
    const uint32_t aDst = sbase + ((asel < 2) ? SM_AH : SM_AL) + ar * PITCH + (asel & 1) * 16;
    // B chunk: 256 pixels x 2 halves
    const int p = tid >> 1, bh_ = tid & 1;
    const int py = p >> 6, px = p & 63;
    const char* bSrc = (const char*)xh + (size_t)b * 1048576 + bh_ * 16;
    const uint32_t bDst = sbase + SM_B + p * PITCH + bh_ * 16;

    const uint32_t offA = (uint32_t)((warp_m * 32 + (lane & 15)) * PITCH + (lane >> 4) * 16);
    const uint32_t offB = (uint32_t)((warp_n * 64 + (lane & 7)) * PITCH + ((lane >> 3) & 1) * 16);

    float C[8][2][4];
#pragma unroll
    for (int i = 0; i < 8; i++)
#pragma unroll
        for (int j = 0; j < 2; j++)
#pragma unroll
            for (int q = 0; q < 4; q++) C[i][j][q] = 0.f;

#define LOAD_STAGE(s, buf) do { \
    int tap_ = (s) >> 3, cb_ = (s) & 7; \
    int dy_ = tap_ / 3 - 1, dx_ = tap_ % 3 - 1; \
    int yy_ = y0 + py + dy_, xx_ = px + dx_; \
    bool v_ = ((unsigned)yy_ < 64u) && ((unsigned)xx_ < 64u); \
    size_t boff_ = (size_t)cb_ * 131072 + (v_ ? (size_t)(yy_ * 64 + xx_) * 32 : 0); \
    unsigned bsz_ = v_ ? 16u : 0u; \
    uint32_t bs_ = (buf) * BUF_SZ; \
    CPA(aDst + bs_, aSrc + (size_t)(s) * 4096, 16u); \
    CPA(bDst + bs_, bSrc + boff_, bsz_); \
} while (0)

    LOAD_STAGE(0, 0); CP_COMMIT();
    LOAD_STAGE(1, 1); CP_COMMIT();
    LOAD_STAGE(2, 2); CP_COMMIT();

    for (int s = 0; s < NSTG; s++) {
        CP_WAIT2();
        __syncthreads();
        if (s + 3 < NSTG) LOAD_STAGE(s + 3, (s + 3) & 3);
        CP_COMMIT();

        const uint32_t bb = sbase + (s & 3) * BUF_SZ;
        uint32_t Ahf[2][4], Alf[2][4];
        LDSM4(Ahf[0], bb + SM_AH + offA);
        LDSM4(Ahf[1], bb + SM_AH + offA + 16 * PITCH);
        LDSM4(Alf[0], bb + SM_AL + offA);
        LDSM4(Alf[1], bb + SM_AL + offA + 16 * PITCH);
#pragma unroll
        for (int ntp = 0; ntp < 4; ntp++) {
            uint32_t BH[2][2];
            LDSM2(BH[0], bb + SM_B + offB + (2 * ntp) * 8 * PITCH);
            LDSM2(BH[1], bb + SM_B + offB + (2 * ntp + 1) * 8 * PITCH);
            float (*c0)[4] = C[2 * ntp];
            float (*c1)[4] = C[2 * ntp + 1];
            MMA(c0[0], Ahf[0], BH[0]); MMA(c0[1], Ahf[1], BH[0]);
            MMA(c1[0], Ahf[0], BH[1]); MMA(c1[1], Ahf[1], BH[1]);
            MMA(c0[0], Alf[0], BH[0]); MMA(c0[1], Alf[1], BH[0]);
            MMA(c1[0], Alf[0], BH[1]); MMA(c1[1], Alf[1], BH[1]);
        }
    }

    // --- epilogue ---
    const int y = y0 + warp_n;
    float* orow = out + (size_t)b * 128 * HW + y * 64;
#pragma unroll
    for (int mt = 0; mt < 2; mt++) {
        int oc0 = warp_m * 32 + mt * 16 + (lane >> 2);
        float bi0 = aggb[b * 128 + oc0];
        float bi1 = aggb[b * 128 + oc0 + 8];
#pragma unroll
        for (int nt = 0; nt < 8; nt++) {
            int xcol = nt * 8 + 2 * (lane & 3);
            float2 v0 = { C[nt][mt][0] + bi0, C[nt][mt][1] + bi0 };
            float2 v1 = { C[nt][mt][2] + bi1, C[nt][mt][3] + bi1 };
            *(float2*)(orow + (size_t)oc0 * HW + xcol) = v0;
            *(float2*)(orow + (size_t)(oc0 + 8) * HW + xcol) = v1;
        }
    }
}

// ---------- host ----------
extern "C" void kernel_launch(void* const* d_in, const int* in_sizes, int n_in,
                              void* d_out, int out_size) {
    const float* x      = (const float*)d_in[0];
    const float* prompt = (const float*)d_in[1];
    const float* w1     = (const float*)d_in[2];
    const float* b1     = (const float*)d_in[3];
    const float* w2     = (const float*)d_in[4];
    const float* b2     = (const float*)d_in[5];
    const float* kw     = (const float*)d_in[6];
    const float* kbias  = (const float*)d_in[7];
    float* out = (float*)d_out;

    float *pooled, *alphas, *aggb;
    __half *xh, *awh, *awl;
    cudaGetSymbolAddress((void**)&pooled, g_pooled);
    cudaGetSymbolAddress((void**)&alphas, g_alphas);
    cudaGetSymbolAddress((void**)&aggb,   g_aggb);
    cudaGetSymbolAddress((void**)&xh,     g_xt);
    cudaGetSymbolAddress((void**)&awh,    g_aw_hi);
    cudaGetSymbolAddress((void**)&awl,    g_aw_lo);

    cudaFuncSetAttribute(conv_mma_kernel, cudaFuncAttributeMaxDynamicSharedMemorySize, 4 * BUF_SZ);

    pool_kernel<<<B_ * C_IN, 256>>>(x, pooled);
    attn_kernel<<<B_, 512>>>(pooled, prompt, w1, b1, w2, b2, kbias, alphas, aggb);
    aggw_f16_kernel<<<dim3(C_OUT, B_), 128>>>(kw, alphas, awh, awl);
    xt_f16_kernel<<<dim3(HW / 32, C_IN / 32, B_), dim3(32, 8)>>>(x, xh);
    conv_mma_kernel<<<512, 512, 4 * BUF_SZ>>>(awh, awl, xh, aggb, out);
}

// round 6
// speedup vs baseline: 2.7772x; 1.1433x over previous
#include <cuda_runtime.h>
#include <cuda_fp16.h>
#include <stdint.h>

#define B_    32
#define C_IN  128
#define H_    64
#define W_    64
#define K_    8
#define C_OUT 128
#define HID   512
#define HW    4096
#define NUNITS 2048
#define GRID_P 296

__device__ float g_pooled[B_ * C_IN];
__device__ float g_alphas[B_ * K_];
__device__ float g_aggb[B_ * C_OUT];
// x: [b][cb(8)][pixel(4096)][ci16] fp16 (1,048,576 B per b)
__device__ __half g_xt[(size_t)B_ * HW * C_IN];
// w: [b][tap(9)][cb(8)][oc(128)][ci16] fp16 (294,912 B per b)
__device__ __half g_aw[(size_t)B_ * 9 * C_OUT * C_IN];

__device__ __forceinline__ uint32_t smem_u32(const void* p) {
    uint32_t a;
    asm("{ .reg .u64 t; cvta.to.shared.u64 t, %1; cvt.u32.u64 %0, t; }" : "=r"(a) : "l"(p));
    return a;
}
#define CPA(dst, src, sz) \
    asm volatile("cp.async.cg.shared.global [%0], [%1], 16, %2;" :: "r"(dst), "l"(src), "r"(sz) : "memory")
#define CP_COMMIT() asm volatile("cp.async.commit_group;" ::: "memory")
#define CP_WAIT2()  asm volatile("cp.async.wait_group 2;" ::: "memory")
#define LDSM4(r, a) \
    asm volatile("ldmatrix.sync.aligned.m8n8.x4.shared.b16 {%0,%1,%2,%3}, [%4];" \
        : "=r"((r)[0]), "=r"((r)[1]), "=r"((r)[2]), "=r"((r)[3]) : "r"(a))
#define LDSM2(r, a) \
    asm volatile("ldmatrix.sync.aligned.m8n8.x2.shared.b16 {%0,%1}, [%2];" \
        : "=r"((r)[0]), "=r"((r)[1]) : "r"(a))
#define MMA(c, a, bb) \
    asm volatile("mma.sync.aligned.m16n8k16.row.col.f32.f16.f16.f32 " \
        "{%0,%1,%2,%3}, {%4,%5,%6,%7}, {%8,%9}, {%0,%1,%2,%3};" \
        : "+f"((c)[0]), "+f"((c)[1]), "+f"((c)[2]), "+f"((c)[3]) \
        : "r"((a)[0]), "r"((a)[1]), "r"((a)[2]), "r"((a)[3]), "r"((bb)[0]), "r"((bb)[1]))

// ---------- 1) pool ----------
__global__ __launch_bounds__(256) void pool_kernel(const float* __restrict__ x, float* __restrict__ pooled) {
    int bc = blockIdx.x;
    const float* p = x + (size_t)bc * HW;
    float s = 0.f;
    for (int i = threadIdx.x; i < HW; i += 256) s += p[i];
#pragma unroll
    for (int o = 16; o; o >>= 1) s += __shfl_xor_sync(~0u, s, o);
    __shared__ float red[8];
    if ((threadIdx.x & 31) == 0) red[threadIdx.x >> 5] = s;
    __syncthreads();
    if (threadIdx.x < 8) {
        s = red[threadIdx.x];
#pragma unroll
        for (int o = 4; o; o >>= 1) s += __shfl_xor_sync(0xffu, s, o);
        if (threadIdx.x == 0) pooled[bc] = s * (1.f / (float)HW);
    }
}

// ---------- 2) attention ----------
__global__ __launch_bounds__(512) void attn_kernel(const float* __restrict__ pooled, const float* __restrict__ prompt,
        const float* __restrict__ w1, const float* __restrict__ b1, const float* __restrict__ w2,
        const float* __restrict__ b2, const float* __restrict__ kbias,
        float* __restrict__ alphas, float* __restrict__ aggb) {
    int b = blockIdx.x, t = threadIdx.x;
    __shared__ float sp[C_IN], sh[HID], ss[HID], sc[K_], sal[K_];
    if (t < C_IN) sp[t] = pooled[b * C_IN + t];
    __syncthreads();
    { const float* wr = w1 + (size_t)t * C_IN; float a = b1[t];
#pragma unroll 8
      for (int i = 0; i < C_IN; i++) a = fmaf(sp[i], wr[i], a);
      sh[t] = fmaxf(a, 0.f); }
    __syncthreads();
    { const float* wr = w2 + (size_t)t * HID; float a = b2[t];
#pragma unroll 8
      for (int i = 0; i < HID; i++) a = fmaf(sh[i], wr[i], a);
      ss[t] = a; }
    __syncthreads();
    int wr = t >> 5, ln = t & 31;
    if (wr < K_) {
        const float* pr = prompt + (size_t)wr * HID;
        float a = 0.f;
        for (int i = ln; i < HID; i += 32) a = fmaf(ss[i], pr[i], a);
#pragma unroll
        for (int o = 16; o; o >>= 1) a += __shfl_xor_sync(~0u, a, o);
        if (ln == 0) sc[wr] = a;
    }
    __syncthreads();
    if (t == 0) {
        float m = sc[0];
#pragma unroll
        for (int k = 1; k < K_; k++) m = fmaxf(m, sc[k]);
        float e[K_], su = 0.f;
#pragma unroll
        for (int k = 0; k < K_; k++) { e[k] = __expf(sc[k] - m); su += e[k]; }
        float inv = 1.f / su;
#pragma unroll
        for (int k = 0; k < K_; k++) { sal[k] = e[k] * inv; alphas[b * K_ + k] = sal[k]; }
    }
    __syncthreads();
    if (t < C_OUT) {
        float a = 0.f;
#pragma unroll
        for (int k = 0; k < K_; k++) a = fmaf(sal[k], kbias[k * C_OUT + t], a);
        aggb[b * C_OUT + t] = a;
    }
}

// ---------- 3) weight agg -> [b][tap][cb][oc][ci16] fp16 ----------
__global__ __launch_bounds__(128) void aggw_f16_kernel(const float* __restrict__ kw, const float* __restrict__ alphas,
        __half* __restrict__ A) {
    int oc = blockIdx.x, b = blockIdx.y, ci = threadIdx.x;
    __shared__ float skw[K_][C_IN * 9];
    __shared__ float a[K_];
    if (ci < K_) a[ci] = alphas[b * K_ + ci];
    for (int k = 0; k < K_; k++)
        for (int i = ci; i < C_IN * 9; i += 128)
            skw[k][i] = kw[(size_t)(k * C_OUT + oc) * (C_IN * 9) + i];
    __syncthreads();
    float acc[9];
#pragma unroll
    for (int t = 0; t < 9; t++) acc[t] = 0.f;
#pragma unroll
    for (int k = 0; k < K_; k++) {
        float al = a[k];
        const float* p = &skw[k][ci * 9];
#pragma unroll
        for (int t = 0; t < 9; t++) acc[t] = fmaf(al, p[t], acc[t]);
    }
#pragma unroll
    for (int t = 0; t < 9; t++) {
        size_t o = ((((size_t)(b * 9 + t) * 8 + (ci >> 4)) * C_OUT) + oc) * 16 + (ci & 15);
        A[o] = __float2half_rn(acc[t]);
    }
}

// ---------- 4) x -> [b][cb][p][ci16] fp16, coalesced 32B writes ----------
__global__ __launch_bounds__(256) void xt_f16_kernel(const float* __restrict__ x, __half* __restrict__ X) {
    __shared__ float t[32][33];
    int b = blockIdx.z, p0 = blockIdx.x * 32, c0 = blockIdx.y * 32;
    int tx = threadIdx.x, ty = threadIdx.y;
    int tid = ty * 32 + tx;
#pragma unroll
    for (int i = 0; i < 4; i++)
        t[ty + 8 * i][tx] = x[((size_t)b * C_IN + c0 + ty + 8 * i) * HW + p0 + tx];
    __syncthreads();
#pragma unroll
    for (int i = 0; i < 2; i++) {
        int idx = tid + 256 * i;          // 0..511
        int sub  = idx & 7;               // ci quad within 16 (2 ci each)
        int pxcb = idx >> 3;
        int pxl  = pxcb & 31;
        int cbl  = pxcb >> 5;             // 0..1
        int cl   = cbl * 16 + sub * 2;    // ci within 32-tile
        int c    = c0 + cl;
        __half2 v = __floats2half2_rn(t[cl][pxl], t[cl + 1][pxl]);
        size_t o = ((((size_t)b * 8 + (c >> 4)) * HW + p0 + pxl) * 16 + (c & 15)) >> 1;
        ((__half2*)X)[o] = v;
    }
}

// ---------- 5) persistent HMMA conv: fp16 1-pass ----------
#define PITCH 48
#define SM_A  0
#define SM_B  6144
#define BUF_SZ 9216
__global__ __launch_bounds__(128, 2) void conv_mma_kernel(
        const __half* __restrict__ aw, const __half* __restrict__ xt,
        const float* __restrict__ aggb, float* __restrict__ out)
{
    extern __shared__ __align__(128) char sm[];
    const uint32_t sbase = smem_u32(sm);
    const int tid = threadIdx.x, wid = tid >> 5, lane = tid & 31;  // wid = warp_m

    const int px = tid >> 1, bhalf = tid & 1;
    const uint32_t aDst = sbase + SM_A + tid * PITCH;
    const uint32_t bDst = sbase + SM_B + px * PITCH + bhalf * 16;
    const uint32_t offA = (uint32_t)((wid * 32 + (lane & 15)) * PITCH + (lane >> 4) * 16);
    const uint32_t offB = (uint32_t)((lane & 7) * PITCH + ((lane >> 3) & 1) * 16);

    int nu = 0;
    for (int u = blockIdx.x; u < NUNITS; u += GRID_P) nu++;
    const int T = nu * 72;

    int l_u = blockIdx.x, l_s = 0, l_idx = 0;
    int c_u = blockIdx.x, c_s = 0;

    float C[8][2][4];
#pragma unroll
    for (int i = 0; i < 8; i++)
#pragma unroll
        for (int j = 0; j < 2; j++)
#pragma unroll
            for (int q = 0; q < 4; q++) C[i][j][q] = 0.f;

#define ISSUE() do { \
    if (l_idx < T) { \
        int b_ = l_u >> 6, y_ = l_u & 63; \
        int tap_ = l_s >> 3, cb_ = l_s & 7; \
        int yy_ = y_ + tap_ / 3 - 1, xx_ = px + tap_ % 3 - 1; \
        bool v_ = ((unsigned)yy_ < 64u) && ((unsigned)xx_ < 64u); \
        size_t boff_ = (size_t)b_ * 1048576 + (size_t)cb_ * 131072 \
                     + (v_ ? (size_t)(yy_ * 64 + xx_) * 32 : 0) + bhalf * 16; \
        unsigned bsz_ = v_ ? 16u : 0u; \
        uint32_t bs_ = (l_idx & 3) * BUF_SZ; \
        const char* as_ = (const char*)aw + (size_t)b_ * 294912 + l_s * 4096 + tid * 32; \
        CPA(aDst + bs_,      as_,      16u); \
        CPA(aDst + bs_ + 16, as_ + 16, 16u); \
        CPA(bDst + bs_, (const char*)xt + boff_, bsz_); \
        l_s++; if (l_s == 72) { l_s = 0; l_u += GRID_P; } \
        l_idx++; \
    } \
} while (0)

    ISSUE(); CP_COMMIT();
    ISSUE(); CP_COMMIT();
    ISSUE(); CP_COMMIT();

    for (int c_idx = 0; c_idx < T; c_idx++) {
        CP_WAIT2();
        __syncthreads();
        ISSUE();
        CP_COMMIT();

        const uint32_t bb = sbase + (c_idx & 3) * BUF_SZ;
        uint32_t Af[2][4];
        LDSM4(Af[0], bb + SM_A + offA);
        LDSM4(Af[1], bb + SM_A + offA + 16 * PITCH);
#pragma unroll
        for (int nt = 0; nt < 8; nt++) {
            uint32_t Bf[2];
            LDSM2(Bf, bb + SM_B + offB + nt * 8 * PITCH);
            MMA(C[nt][0], Af[0], Bf);
            MMA(C[nt][1], Af[1], Bf);
        }

        if (++c_s == 72) {
            // epilogue for unit c_u: row y, warp's 32 oc
            int b_ = c_u >> 6, y_ = c_u & 63;
            float* orow = out + (size_t)b_ * 128 * HW + y_ * 64;
#pragma unroll
            for (int mt = 0; mt < 2; mt++) {
                int oc0 = wid * 32 + mt * 16 + (lane >> 2);
                float bi0 = aggb[b_ * 128 + oc0];
                float bi1 = aggb[b_ * 128 + oc0 + 8];
#pragma unroll
                for (int nt = 0; nt < 8; nt++) {
                    int xcol = nt * 8 + 2 * (lane & 3);
                    float2 v0 = { C[nt][mt][0] + bi0, C[nt][mt][1] + bi0 };
                    float2 v1 = { C[nt][mt][2] + bi1, C[nt][mt][3] + bi1 };
                    *(float2*)(orow + (size_t)oc0 * HW + xcol) = v0;
                    *(float2*)(orow + (size_t)(oc0 + 8) * HW + xcol) = v1;
                }
            }
#pragma unroll
            for (int i = 0; i < 8; i++)
#pragma unroll
                for (int j = 0; j < 2; j++)
#pragma unroll
                    for (int q = 0; q < 4; q++) C[i][j][q] = 0.f;
            c_s = 0; c_u += GRID_P;
        }
    }
}

// ---------- host ----------
extern "C" void kernel_launch(void* const* d_in, const int* in_sizes, int n_in,
                              void* d_out, int out_size) {
    const float* x      = (const float*)d_in[0];
    const float* prompt = (const float*)d_in[1];
    const float* w1     = (const float*)d_in[2];
    const float* b1     = (const float*)d_in[3];
    const float* w2     = (const float*)d_in[4];
    const float* b2     = (const float*)d_in[5];
    const float* kw     = (const float*)d_in[6];
    const float* kbias  = (const float*)d_in[7];
    float* out = (float*)d_out;

    float *pooled, *alphas, *aggb;
    __half *xh, *awp;
    cudaGetSymbolAddress((void**)&pooled, g_pooled);
    cudaGetSymbolAddress((void**)&alphas, g_alphas);
    cudaGetSymbolAddress((void**)&aggb,   g_aggb);
    cudaGetSymbolAddress((void**)&xh,     g_xt);
    cudaGetSymbolAddress((void**)&awp,    g_aw);

    cudaFuncSetAttribute(conv_mma_kernel, cudaFuncAttributeMaxDynamicSharedMemorySize, 4 * BUF_SZ);

    pool_kernel<<<B_ * C_IN, 256>>>(x, pooled);
    attn_kernel<<<B_, 512>>>(pooled, prompt, w1, b1, w2, b2, kbias, alphas, aggb);
    aggw_f16_kernel<<<dim3(C_OUT, B_), 128>>>(kw, alphas, awp);
    xt_f16_kernel<<<dim3(HW / 32, C_IN / 32, B_), dim3(32, 8)>>>(x, xh);
    conv_mma_kernel<<<GRID_P, 128, 4 * BUF_SZ>>>(awp, xh, aggb, out);
}

// round 7
// speedup vs baseline: 3.2589x; 1.1734x over previous
#include <cuda_runtime.h>
#include <cuda_fp16.h>
#include <stdint.h>

#define B_    32
#define C_IN  128
#define H_    64
#define W_    64
#define K_    8
#define C_OUT 128
#define HID   512
#define HW    4096
#define NUNITS 1024         // unit = 2 rows (128 px)
#define GRID_P 296

__device__ float g_pooled[B_ * C_IN];
__device__ float g_alphas[B_ * K_];
__device__ float g_aggb[B_ * C_OUT];
__device__ int   g_ctr;
// x: [b][cb(8)][pixel(4096)][ci16] fp16 (1,048,576 B per b)
__device__ __half g_xt[(size_t)B_ * HW * C_IN];
// w: [b][tap(9)][cb(8)][oc(128)][ci16] fp16 (294,912 B per b; 4096 B per stage)
__device__ __half g_aw[(size_t)B_ * 9 * C_OUT * C_IN];

__device__ __forceinline__ uint32_t smem_u32(const void* p) {
    uint32_t a;
    asm("{ .reg .u64 t; cvta.to.shared.u64 t, %1; cvt.u32.u64 %0, t; }" : "=r"(a) : "l"(p));
    return a;
}
#define CPA(dst, src, sz) \
    asm volatile("cp.async.cg.shared.global [%0], [%1], 16, %2;" :: "r"(dst), "l"(src), "r"(sz) : "memory")
#define CP_COMMIT() asm volatile("cp.async.commit_group;" ::: "memory")
#define CP_WAIT2()  asm volatile("cp.async.wait_group 2;" ::: "memory")
#define LDSM4(r, a) \
    asm volatile("ldmatrix.sync.aligned.m8n8.x4.shared.b16 {%0,%1,%2,%3}, [%4];" \
        : "=r"((r)[0]), "=r"((r)[1]), "=r"((r)[2]), "=r"((r)[3]) : "r"(a))
#define LDSM2(r, a) \
    asm volatile("ldmatrix.sync.aligned.m8n8.x2.shared.b16 {%0,%1}, [%2];" \
        : "=r"((r)[0]), "=r"((r)[1]) : "r"(a))
#define MMA(c, a, bb) \
    asm volatile("mma.sync.aligned.m16n8k16.row.col.f32.f16.f16.f32 " \
        "{%0,%1,%2,%3}, {%4,%5,%6,%7}, {%8,%9}, {%0,%1,%2,%3};" \
        : "+f"((c)[0]), "+f"((c)[1]), "+f"((c)[2]), "+f"((c)[3]) \
        : "r"((a)[0]), "r"((a)[1]), "r"((a)[2]), "r"((a)[3]), "r"((bb)[0]), "r"((bb)[1]))

// ---------- 1) pool ----------
__global__ __launch_bounds__(256) void pool_kernel(const float* __restrict__ x, float* __restrict__ pooled) {
    int bc = blockIdx.x;
    const float* p = x + (size_t)bc * HW;
    float s = 0.f;
    for (int i = threadIdx.x; i < HW; i += 256) s += p[i];
#pragma unroll
    for (int o = 16; o; o >>= 1) s += __shfl_xor_sync(~0u, s, o);
    __shared__ float red[8];
    if ((threadIdx.x & 31) == 0) red[threadIdx.x >> 5] = s;
    __syncthreads();
    if (threadIdx.x < 8) {
        s = red[threadIdx.x];
#pragma unroll
        for (int o = 4; o; o >>= 1) s += __shfl_xor_sync(0xffu, s, o);
        if (threadIdx.x == 0) pooled[bc] = s * (1.f / (float)HW);
    }
}

// ---------- 2) attention ----------
__global__ __launch_bounds__(512) void attn_kernel(const float* __restrict__ pooled, const float* __restrict__ prompt,
        const float* __restrict__ w1, const float* __restrict__ b1, const float* __restrict__ w2,
        const float* __restrict__ b2, const float* __restrict__ kbias,
        float* __restrict__ alphas, float* __restrict__ aggb) {
    int b = blockIdx.x, t = threadIdx.x;
    __shared__ float sp[C_IN], sh[HID], ss[HID], sc[K_], sal[K_];
    if (t < C_IN) sp[t] = pooled[b * C_IN + t];
    __syncthreads();
    { const float* wr = w1 + (size_t)t * C_IN; float a = b1[t];
#pragma unroll 8
      for (int i = 0; i < C_IN; i++) a = fmaf(sp[i], wr[i], a);
      sh[t] = fmaxf(a, 0.f); }
    __syncthreads();
    { const float* wr = w2 + (size_t)t * HID; float a = b2[t];
#pragma unroll 8
      for (int i = 0; i < HID; i++) a = fmaf(sh[i], wr[i], a);
      ss[t] = a; }
    __syncthreads();
    int wr = t >> 5, ln = t & 31;
    if (wr < K_) {
        const float* pr = prompt + (size_t)wr * HID;
        float a = 0.f;
        for (int i = ln; i < HID; i += 32) a = fmaf(ss[i], pr[i], a);
#pragma unroll
        for (int o = 16; o; o >>= 1) a += __shfl_xor_sync(~0u, a, o);
        if (ln == 0) sc[wr] = a;
    }
    __syncthreads();
    if (t == 0) {
        float m = sc[0];
#pragma unroll
        for (int k = 1; k < K_; k++) m = fmaxf(m, sc[k]);
        float e[K_], su = 0.f;
#pragma unroll
        for (int k = 0; k < K_; k++) { e[k] = __expf(sc[k] - m); su += e[k]; }
        float inv = 1.f / su;
#pragma unroll
        for (int k = 0; k < K_; k++) { sal[k] = e[k] * inv; alphas[b * K_ + k] = sal[k]; }
    }
    __syncthreads();
    if (t < C_OUT) {
        float a = 0.f;
#pragma unroll
        for (int k = 0; k < K_; k++) a = fmaf(sal[k], kbias[k * C_OUT + t], a);
        aggb[b * C_OUT + t] = a;
    }
}

// ---------- 3) weight agg -> [b][tap][cb][oc][ci16] fp16 ----------
__global__ __launch_bounds__(128) void aggw_f16_kernel(const float* __restrict__ kw, const float* __restrict__ alphas,
        __half* __restrict__ A) {
    int oc = blockIdx.x, b = blockIdx.y, ci = threadIdx.x;
    __shared__ float skw[K_][C_IN * 9];
    __shared__ float a[K_];
    if (ci < K_) a[ci] = alphas[b * K_ + ci];
    for (int k = 0; k < K_; k++)
        for (int i = ci; i < C_IN * 9; i += 128)
            skw[k][i] = kw[(size_t)(k * C_OUT + oc) * (C_IN * 9) + i];
    __syncthreads();
    float acc[9];
#pragma unroll
    for (int t = 0; t < 9; t++) acc[t] = 0.f;
#pragma unroll
    for (int k = 0; k < K_; k++) {
        float al = a[k];
        const float* p = &skw[k][ci * 9];
#pragma unroll
        for (int t = 0; t < 9; t++) acc[t] = fmaf(al, p[t], acc[t]);
    }
#pragma unroll
    for (int t = 0; t < 9; t++) {
        size_t o = ((((size_t)(b * 9 + t) * 8 + (ci >> 4)) * C_OUT) + oc) * 16 + (ci & 15);
        A[o] = __float2half_rn(acc[t]);
    }
}

// ---------- 4) x -> [b][cb][p][ci16] fp16 ----------
__global__ __launch_bounds__(256) void xt_f16_kernel(const float* __restrict__ x, __half* __restrict__ X) {
    __shared__ float t[32][33];
    int b = blockIdx.z, p0 = blockIdx.x * 32, c0 = blockIdx.y * 32;
    int tx = threadIdx.x, ty = threadIdx.y;
    int tid = ty * 32 + tx;
#pragma unroll
    for (int i = 0; i < 4; i++)
        t[ty + 8 * i][tx] = x[((size_t)b * C_IN + c0 + ty + 8 * i) * HW + p0 + tx];
    __syncthreads();
#pragma unroll
    for (int i = 0; i < 2; i++) {
        int idx = tid + 256 * i;
        int sub  = idx & 7;
        int pxcb = idx >> 3;
        int pxl  = pxcb & 31;
        int cbl  = pxcb >> 5;
        int cl   = cbl * 16 + sub * 2;
        int c    = c0 + cl;
        __half2 v = __floats2half2_rn(t[cl][pxl], t[cl + 1][pxl]);
        size_t o = ((((size_t)b * 8 + (c >> 4)) * HW + p0 + pxl) * 16 + (c & 15)) >> 1;
        ((__half2*)X)[o] = v;
    }
}

// ---------- counter reset ----------
__global__ void reset_ctr_kernel() { g_ctr = 0; }

// ---------- 5) persistent HMMA conv: fp16 1-pass, dynamic stealing ----------
#define PITCH 48
#define SM_A  0
#define SM_B  6144
#define BUF_SZ 12288
__global__ __launch_bounds__(256, 2) void conv_mma_kernel(
        const __half* __restrict__ aw, const __half* __restrict__ xt,
        const float* __restrict__ aggb, float* __restrict__ out)
{
    extern __shared__ __align__(128) char sm[];
    const uint32_t sbase = smem_u32(sm);
    __shared__ int s_nu[2];
    const int tid = threadIdx.x, wid = tid >> 5, lane = tid & 31;
    const int warp_m = wid & 3, warp_n = wid >> 2;

    const int row  = tid >> 1, half = tid & 1;      // for A and B staging
    const uint32_t aDst = sbase + SM_A + row * PITCH + half * 16;
    const uint32_t bDst = sbase + SM_B + row * PITCH + half * 16;
    const uint32_t offA = (uint32_t)((warp_m * 32 + (lane & 15)) * PITCH + (lane >> 4) * 16);
    const uint32_t offB = (uint32_t)((warp_n * 64 + (lane & 7)) * PITCH + ((lane >> 3) & 1) * 16);

    if (tid == 0) s_nu[0] = atomicAdd(&g_ctr, 1);
    __syncthreads();
    int c_u = s_nu[0];
    if (tid == 0) s_nu[1] = atomicAdd(&g_ctr, 1);
    int nslot = 1;

    int l_u = c_u, l_s = 0, l_buf = 0;

    float C[8][2][4];
#pragma unroll
    for (int i = 0; i < 8; i++)
#pragma unroll
        for (int j = 0; j < 2; j++)
#pragma unroll
            for (int q = 0; q < 4; q++) C[i][j][q] = 0.f;

#define ISSUE() do { \
    if (l_u < NUNITS) { \
        int b_ = l_u >> 5, y0_ = (l_u & 31) * 2; \
        int tap_ = l_s >> 3, cb_ = l_s & 7; \
        int yy_ = y0_ + (row >> 6) + tap_ / 3 - 1; \
        int xx_ = (row & 63) + tap_ % 3 - 1; \
        bool v_ = ((unsigned)yy_ < 64u) && ((unsigned)xx_ < 64u); \
        size_t boff_ = (size_t)b_ * 1048576 + (size_t)cb_ * 131072 \
                     + (v_ ? (size_t)(yy_ * 64 + xx_) * 32 : 0) + half * 16; \
        unsigned bsz_ = v_ ? 16u : 0u; \
        uint32_t bs_ = l_buf * BUF_SZ; \
        CPA(aDst + bs_, (const char*)aw + (size_t)b_ * 294912 + l_s * 4096 + row * 32 + half * 16, 16u); \
        CPA(bDst + bs_, (const char*)xt + boff_, bsz_); \
    } \
    l_s++; l_buf = (l_buf + 1) & 3; \
} while (0)

    // prime 3 stages (l_s cannot wrap: 72 stages/unit)
    ISSUE(); CP_COMMIT();
    ISSUE(); CP_COMMIT();
    ISSUE(); CP_COMMIT();

    int c_buf = 0;
    while (c_u < NUNITS) {
        for (int c_s = 0; c_s < 72; c_s++) {
            CP_WAIT2();
            __syncthreads();
            if (l_s == 72) { l_u = s_nu[nslot]; l_s = 0; }   // safe: many syncs since grab
            ISSUE();
            CP_COMMIT();

            const uint32_t bb = sbase + c_buf * BUF_SZ;
            c_buf = (c_buf + 1) & 3;
            uint32_t Af[2][4];
            LDSM4(Af[0], bb + SM_A + offA);
            LDSM4(Af[1], bb + SM_A + offA + 16 * PITCH);
#pragma unroll
            for (int nt = 0; nt < 8; nt++) {
                uint32_t Bf[2];
                LDSM2(Bf, bb + SM_B + offB + nt * 8 * PITCH);
                MMA(C[nt][0], Af[0], Bf);
                MMA(C[nt][1], Af[1], Bf);
            }
        }

        // epilogue for unit c_u: rows y0, y0+1 (warp_n selects row)
        {
            int b_ = c_u >> 5, y_ = (c_u & 31) * 2 + warp_n;
            float* orow = out + (size_t)b_ * 128 * HW + y_ * 64;
#pragma unroll
            for (int mt = 0; mt < 2; mt++) {
                int oc0 = warp_m * 32 + mt * 16 + (lane >> 2);
                float bi0 = aggb[b_ * 128 + oc0];
                float bi1 = aggb[b_ * 128 + oc0 + 8];
#pragma unroll
                for (int nt = 0; nt < 8; nt++) {
                    int xcol = nt * 8 + 2 * (lane & 3);
                    float2 v0 = { C[nt][0][0 + 4 * mt - 4 * mt] , 0.f };
                    // (rewritten below without aliasing confusion)
                    (void)v0;
                    float2 w0 = { C[nt][mt][0] + bi0, C[nt][mt][1] + bi0 };
                    float2 w1 = { C[nt][mt][2] + bi1, C[nt][mt][3] + bi1 };
                    *(float2*)(orow + (size_t)oc0 * HW + xcol) = w0;
                    *(float2*)(orow + (size_t)(oc0 + 8) * HW + xcol) = w1;
                }
            }
        }
#pragma unroll
        for (int i = 0; i < 8; i++)
#pragma unroll
            for (int j = 0; j < 2; j++)
#pragma unroll
                for (int q = 0; q < 4; q++) C[i][j][q] = 0.f;

        c_u = s_nu[nslot];
        nslot ^= 1;
        if (tid == 0) s_nu[nslot] = atomicAdd(&g_ctr, 1);
        // visibility guaranteed: next read of s_nu[nslot] is >= 69 syncthreads away
    }
}

// ---------- host ----------
extern "C" void kernel_launch(void* const* d_in, const int* in_sizes, int n_in,
                              void* d_out, int out_size) {
    const float* x      = (const float*)d_in[0];
    const float* prompt = (const float*)d_in[1];
    const float* w1     = (const float*)d_in[2];
    const float* b1     = (const float*)d_in[3];
    const float* w2     = (const float*)d_in[4];
    const float* b2     = (const float*)d_in[5];
    const float* kw     = (const float*)d_in[6];
    const float* kbias  = (const float*)d_in[7];
    float* out = (float*)d_out;

    float *pooled, *alphas, *aggb;
    __half *xh, *awp;
    cudaGetSymbolAddress((void**)&pooled, g_pooled);
    cudaGetSymbolAddress((void**)&alphas, g_alphas);
    cudaGetSymbolAddress((void**)&aggb,   g_aggb);
    cudaGetSymbolAddress((void**)&xh,     g_xt);
    cudaGetSymbolAddress((void**)&awp,    g_aw);

    cudaFuncSetAttribute(conv_mma_kernel, cudaFuncAttributeMaxDynamicSharedMemorySize, 4 * BUF_SZ);

    pool_kernel<<<B_ * C_IN, 256>>>(x, pooled);
    attn_kernel<<<B_, 512>>>(pooled, prompt, w1, b1, w2, b2, kbias, alphas, aggb);
    aggw_f16_kernel<<<dim3(C_OUT, B_), 128>>>(kw, alphas, awp);
    xt_f16_kernel<<<dim3(HW / 32, C_IN / 32, B_), dim3(32, 8)>>>(x, xh);
    reset_ctr_kernel<<<1, 1>>>();
    conv_mma_kernel<<<GRID_P, 256, 4 * BUF_SZ>>>(awp, xh, aggb, out);
}